// round 4
// baseline (speedup 1.0000x reference)
#include <cuda_runtime.h>
#include <cstdint>

#define DIMS   1000
#define NLEV   10
#define NPIX   784
#define NBATCH 256
#define NCLS   10
#define PW     25      // 784 pixels -> 25 x u32 words
#define PWP    28      // padded row stride (28*4 = 112B, 16B multiple)

// ---------------- device scratch (no allocations allowed) ----------------
__device__ uint32_t g_posb[1024 * PWP];   // packed position sign bits, d-major rows
__device__ int      g_tpos[1024];         // Tpos[d] = sum_p position[p,d]
__device__ uint32_t g_sig[1024];          // 10-bit vt sign signature per dim
__device__ float    g_wt[1024 * 12];      // W transposed: g_wt[d*12 + c], padded

// ---------------- kernel A1: pack position sign bits --------------------
// Explicit 32-wide register batch: all loads independent -> MLP=32.
__global__ __launch_bounds__(256) void pack_pos_kernel(const float* __restrict__ position) {
    int w = blockIdx.x;                         // word 0..24
    int d = blockIdx.y * 256 + threadIdx.x;     // dim 0..1023
    if (d >= DIMS) return;
    int pbase = w * 32;
    float v[32];
#pragma unroll
    for (int j = 0; j < 32; j++) {
        int p = pbase + j;
        v[j] = (p < NPIX) ? position[p * DIMS + d] : -1.0f;
    }
    uint32_t bits = 0;
#pragma unroll
    for (int j = 0; j < 32; j++)
        bits |= (v[j] > 0.0f ? 1u : 0u) << j;
    g_posb[d * PWP + w] = bits;
}

// ---------------- kernel A2: padding, Tpos, signatures, W^T -------------
__global__ __launch_bounds__(256) void prep_kernel(const float* __restrict__ vt,
                                                   const float* __restrict__ W) {
    int d = blockIdx.x * 256 + threadIdx.x;
    if (d >= 1024) return;
    g_posb[d * PWP + 25] = 0u;
    g_posb[d * PWP + 26] = 0u;
    g_posb[d * PWP + 27] = 0u;
    if (d >= DIMS) {               // pad rows fully zero
#pragma unroll
        for (int w = 0; w < PW; w++) g_posb[d * PWP + w] = 0u;
        g_tpos[d] = 0; g_sig[d] = 0;
        return;
    }
    uint32_t pw[PW];
#pragma unroll
    for (int w = 0; w < PW; w++) pw[w] = g_posb[d * PWP + w];   // independent loads
    float vv[NLEV];
#pragma unroll
    for (int l = 0; l < NLEV; l++) vv[l] = vt[l * DIMS + d];
    float wv[NCLS];
#pragma unroll
    for (int c = 0; c < NCLS; c++) wv[c] = W[c * DIMS + d];

    int tot = 0;
#pragma unroll
    for (int w = 0; w < PW; w++) tot += __popc(pw[w]);
    g_tpos[d] = 2 * tot - NPIX;    // = sum_p position[p,d]
    uint32_t sig = 0;
#pragma unroll
    for (int l = 0; l < NLEV; l++)
        sig |= (vv[l] > 0.0f ? 1u : 0u) << l;
    g_sig[d] = sig;
#pragma unroll
    for (int c = 0; c < NCLS; c++) g_wt[d * 12 + c] = wv[c];
    g_wt[d * 12 + 10] = 0.0f;
    g_wt[d * 12 + 11] = 0.0f;
}

// ---------------- kernel B: masks + half-sig unions + popcount core -----
// 2 batches per CTA; all tables in STATIC shared memory (~17.8KB).
__global__ __launch_bounds__(256) void hdc_kernel(const float* __restrict__ x,
                                                  float* __restrict__ out) {
    // [batch][half: 0=lo,1=hi][32 sigs][PWP words]
    __shared__ __align__(16) uint32_t Mun[2][2][32][PWP];
    __shared__ int      Cun[2][2][32];
    __shared__ __align__(16) uint32_t mask[2][NLEV][PWP];
    __shared__ int      cnt[2][NLEV];
    __shared__ float    wred[2][8][NCLS];

    const int tid  = threadIdx.x;
    const int lane = tid & 31;
    const int warp = tid >> 5;

    // ---- init: zero masks (incl. padding words) ----
    for (int i = tid; i < 2 * NLEV * PWP; i += 256)
        ((uint32_t*)mask)[i] = 0u;
    __syncthreads();

    // ---- phase 1: per-batch level masks via ballot ----
#pragma unroll
    for (int bi = 0; bi < 2; bi++) {
        const float* xb = x + (blockIdx.x * 2 + bi) * NPIX;
        for (int base = 0; base < 1024; base += 256) {
            int p = base + tid;
            int lvl = -1;
            if (p < NPIX) {
                float xv = xb[p];
                int q = (int)rintf(xv * 9.0f);   // round-half-even == jnp.round
                q = q < 0 ? 0 : (q > 9 ? 9 : q);
                lvl = q;
            }
            int word = (base >> 5) + warp;
#pragma unroll
            for (int l = 0; l < NLEV; l++) {
                unsigned bm = __ballot_sync(0xffffffffu, lvl == l);
                if (lane == 0 && word < PW) mask[bi][l][word] = bm;
            }
        }
    }
    __syncthreads();

    if (tid < 2 * NLEV) {
        int bi = tid / NLEV, l = tid % NLEV;
        int c = 0;
#pragma unroll
        for (int w = 0; w < PW; w++) c += __popc(mask[bi][l][w]);
        cnt[bi][l] = c;
    }
    __syncthreads();

    // ---- phase 2: direct unions for each 5-bit half signature ----
    if (tid < 128) {
        int bi   = tid >> 6;            // 0..1
        int half = (tid >> 5) & 1;      // 0..1
        int sg   = tid & 31;            // 0..31
        int lbase = half * 5;
        int c = 0;
#pragma unroll
        for (int l = 0; l < 5; l++)
            if (sg & (1 << l)) c += cnt[bi][lbase + l];
        Cun[bi][half][sg] = c;
        uint4* dst = (uint4*)&Mun[bi][half][sg][0];
#pragma unroll
        for (int q = 0; q < 7; q++) {
            uint4 r = make_uint4(0u, 0u, 0u, 0u);
#pragma unroll
            for (int l = 0; l < 5; l++) {
                if (sg & (1 << l)) {
                    uint4 m = ((const uint4*)&mask[bi][lbase + l][0])[q];
                    r.x |= m.x; r.y |= m.y; r.z |= m.z; r.w |= m.w;
                }
            }
            dst[q] = r;
        }
    }
    __syncthreads();

    // ---- phase 3: fused-LOP3 popcount core + classifier partials ----
    // lo and hi unions are DISJOINT (level masks partition pixels), so
    // popc(lo&p)+popc(hi&p) == popc((lo|hi)&p): one LOP3 + one POPC per word.
    float part[2][NCLS];
#pragma unroll
    for (int bi = 0; bi < 2; bi++)
#pragma unroll
        for (int c = 0; c < NCLS; c++) part[bi][c] = 0.0f;

    if (tid < 250) {
#pragma unroll
        for (int i = 0; i < 4; i++) {
            int d = i * 250 + tid;                 // d < 1000
            uint32_t sig = g_sig[d];
            int siglo = sig & 31, sighi = (sig >> 5) & 31;
            uint4 pb[7];
#pragma unroll
            for (int q = 0; q < 7; q++)
                pb[q] = ((const uint4*)&g_posb[d * PWP])[q];
            int tpos = g_tpos[d];
            const float4* w4 = (const float4*)&g_wt[d * 12];
            float4 w0 = w4[0], w1 = w4[1], w2 = w4[2];
#pragma unroll
            for (int bi = 0; bi < 2; bi++) {
                const uint4* lo4 = (const uint4*)&Mun[bi][0][siglo][0];
                const uint4* hi4 = (const uint4*)&Mun[bi][1][sighi][0];
                int acc = 0;
#pragma unroll
                for (int q = 0; q < 7; q++) {
                    uint4 a = lo4[q], b = hi4[q], p = pb[q];
                    acc += __popc((a.x | b.x) & p.x)
                         + __popc((a.y | b.y) & p.y)
                         + __popc((a.z | b.z) & p.z)
                         + __popc((a.w | b.w) & p.w);
                }
                int csum = Cun[bi][0][siglo] + Cun[bi][1][sighi];
                int s = 4 * acc - 2 * csum - tpos;
                float enc = (s > 0) ? 1.0f : -1.0f;
                part[bi][0] += enc * w0.x; part[bi][1] += enc * w0.y;
                part[bi][2] += enc * w0.z; part[bi][3] += enc * w0.w;
                part[bi][4] += enc * w1.x; part[bi][5] += enc * w1.y;
                part[bi][6] += enc * w1.z; part[bi][7] += enc * w1.w;
                part[bi][8] += enc * w2.x; part[bi][9] += enc * w2.y;
            }
        }
    }

    // ---- deterministic reduction: warp shuffle + fixed-order smem sum ----
#pragma unroll
    for (int bi = 0; bi < 2; bi++) {
#pragma unroll
        for (int c = 0; c < NCLS; c++) {
            float v = part[bi][c];
            v += __shfl_down_sync(0xffffffffu, v, 16);
            v += __shfl_down_sync(0xffffffffu, v, 8);
            v += __shfl_down_sync(0xffffffffu, v, 4);
            v += __shfl_down_sync(0xffffffffu, v, 2);
            v += __shfl_down_sync(0xffffffffu, v, 1);
            if (lane == 0) wred[bi][warp][c] = v;
        }
    }
    __syncthreads();

    if (tid < 2 * NCLS) {
        int bi = tid / NCLS, c = tid % NCLS;
        float s = 0.0f;
#pragma unroll
        for (int w = 0; w < 8; w++) s += wred[bi][w][c];
        out[(blockIdx.x * 2 + bi) * NCLS + c] = s;
    }
}

// ---------------- launch ----------------
extern "C" void kernel_launch(void* const* d_in, const int* in_sizes, int n_in,
                              void* d_out, int out_size) {
    const float* x        = (const float*)d_in[0];   // [256, 28, 28]
    const float* position = (const float*)d_in[1];   // [784, 1000]
    const float* vt       = (const float*)d_in[2];   // [10, 1000]
    const float* W        = (const float*)d_in[3];   // [10, 1000]
    float* out = (float*)d_out;                      // [256, 10]

    pack_pos_kernel<<<dim3(25, 4), 256>>>(position);
    prep_kernel<<<4, 256>>>(vt, W);
    hdc_kernel<<<128, 256>>>(x, out);
}

// round 6
// speedup vs baseline: 1.1043x; 1.1043x over previous
#include <cuda_runtime.h>
#include <cstdint>

#define DIMS   1000
#define NLEV   10
#define NPIX   784
#define NBATCH 256
#define NCLS   10
#define PW     25      // 784 pixels -> 25 x u32 words
#define PWP    28      // g_posb row stride in words (112B, 16B multiple)

// ---------------- device scratch (no allocations allowed) ----------------
__device__ uint32_t g_posb[1024 * PWP];   // packed position sign bits, d-major rows
__device__ int      g_tpos[1024];         // Tpos[d] = sum_p position[p,d]
__device__ uint32_t g_sig[1024];          // 10-bit vt sign signature per dim
__device__ float    g_wt[1024 * 12];      // W transposed: g_wt[d*12 + c], padded

// ---------------- kernel A1: pack position sign bits --------------------
// 1 thread = 4 dims (float4 loads), full 32-deep MLP: whole 3.2MB in flight.
__global__ __launch_bounds__(256, 1) void pack_pos_kernel(const float* __restrict__ position) {
    int w  = blockIdx.x;               // word 0..24
    int t  = threadIdx.x;              // 0..255 -> dims 4t..4t+3
    if (t >= 250) return;              // dims 0..999 only (no OOB)
    int d0 = t * 4;
    int pbase = w * 32;
    float4 v[32];
#pragma unroll
    for (int j = 0; j < 32; j++) {
        int p = pbase + j;
        if (p < NPIX)
            v[j] = *(const float4*)(position + (size_t)p * DIMS + d0);
        else
            v[j] = make_float4(-1.f, -1.f, -1.f, -1.f);
    }
    uint32_t b0 = 0, b1 = 0, b2 = 0, b3 = 0;
#pragma unroll
    for (int j = 0; j < 32; j++) {
        b0 |= (v[j].x > 0.0f ? 1u : 0u) << j;
        b1 |= (v[j].y > 0.0f ? 1u : 0u) << j;
        b2 |= (v[j].z > 0.0f ? 1u : 0u) << j;
        b3 |= (v[j].w > 0.0f ? 1u : 0u) << j;
    }
    g_posb[(d0 + 0) * PWP + w] = b0;
    g_posb[(d0 + 1) * PWP + w] = b1;
    g_posb[(d0 + 2) * PWP + w] = b2;
    g_posb[(d0 + 3) * PWP + w] = b3;
}

// ---------------- kernel A2: Tpos, signatures, W^T ----------------------
__global__ __launch_bounds__(256) void prep_kernel(const float* __restrict__ vt,
                                                   const float* __restrict__ W) {
    int d = blockIdx.x * 256 + threadIdx.x;
    if (d >= DIMS) return;
    uint32_t pw[PW];
#pragma unroll
    for (int w = 0; w < PW; w++) pw[w] = g_posb[d * PWP + w];   // independent loads
    float vv[NLEV];
#pragma unroll
    for (int l = 0; l < NLEV; l++) vv[l] = vt[l * DIMS + d];
    float wv[NCLS];
#pragma unroll
    for (int c = 0; c < NCLS; c++) wv[c] = W[c * DIMS + d];

    int tot = 0;
#pragma unroll
    for (int w = 0; w < PW; w++) tot += __popc(pw[w]);
    g_tpos[d] = 2 * tot - NPIX;        // = sum_p position[p,d]
    uint32_t sig = 0;
#pragma unroll
    for (int l = 0; l < NLEV; l++)
        sig |= (vv[l] > 0.0f ? 1u : 0u) << l;
    g_sig[d] = sig;
#pragma unroll
    for (int c = 0; c < NCLS; c++) g_wt[d * 12 + c] = wv[c];
    g_wt[d * 12 + 10] = 0.0f;
    g_wt[d * 12 + 11] = 0.0f;
}

// ---------------- kernel B: masks + transposed union tables + popcount --
// MunT layout: [bi][half][word][sg] -- sg is the fast (bank) axis, so lanes
// with distinct signatures hit distinct banks (conflict-free), equal sigs
// broadcast. All tables static shared (~16KB).
__global__ __launch_bounds__(256) void hdc_kernel(const float* __restrict__ x,
                                                  float* __restrict__ out) {
    __shared__ uint32_t MunT[2][2][PW][32];   // 12.5KB
    __shared__ int      Cun[2][2][32];
    __shared__ __align__(16) uint32_t mask[2][NLEV][PWP];
    __shared__ int      cnt[2][NLEV];
    __shared__ float    wred[2][8][NCLS];

    const int tid  = threadIdx.x;
    const int lane = tid & 31;
    const int warp = tid >> 5;

    // ---- init: zero level masks (incl. padding words) ----
    for (int i = tid; i < 2 * NLEV * PWP; i += 256)
        ((uint32_t*)mask)[i] = 0u;
    __syncthreads();

    // ---- phase 1: per-batch level masks via ballot ----
#pragma unroll
    for (int bi = 0; bi < 2; bi++) {
        const float* xb = x + (blockIdx.x * 2 + bi) * NPIX;
        for (int base = 0; base < 1024; base += 256) {
            int p = base + tid;
            int lvl = -1;
            if (p < NPIX) {
                float xv = xb[p];
                int q = (int)rintf(xv * 9.0f);   // round-half-even == jnp.round
                q = q < 0 ? 0 : (q > 9 ? 9 : q);
                lvl = q;
            }
            int word = (base >> 5) + warp;
#pragma unroll
            for (int l = 0; l < NLEV; l++) {
                unsigned bm = __ballot_sync(0xffffffffu, lvl == l);
                if (lane == 0 && word < PW) mask[bi][l][word] = bm;
            }
        }
    }
    __syncthreads();

    if (tid < 2 * NLEV) {
        int bi = tid / NLEV, l = tid % NLEV;
        int c = 0;
#pragma unroll
        for (int w = 0; w < PW; w++) c += __popc(mask[bi][l][w]);
        cnt[bi][l] = c;
    }
    __syncthreads();

    // ---- phase 2: unions for each 5-bit half signature (transposed) ----
    // 128 threads: (bi, half, sg). Lanes in a warp share (bi,half) -> mask
    // reads broadcast; writes go to distinct sg -> distinct banks.
    if (tid < 128) {
        int bi   = tid >> 6;            // 0..1
        int half = (tid >> 5) & 1;      // 0..1
        int sg   = tid & 31;            // 0..31
        int lbase = half * 5;
        int c = 0;
#pragma unroll
        for (int l = 0; l < 5; l++)
            if (sg & (1 << l)) c += cnt[bi][lbase + l];
        Cun[bi][half][sg] = c;
#pragma unroll
        for (int q = 0; q < PW; q++) {
            uint32_t r = 0u;
#pragma unroll
            for (int l = 0; l < 5; l++)
                if (sg & (1 << l)) r |= mask[bi][lbase + l][q];
            MunT[bi][half][q][sg] = r;
        }
    }
    __syncthreads();

    // ---- phase 3: conflict-free popcount core + classifier partials ----
    // lo/hi unions are disjoint => popc(lo&p)+popc(hi&p) == popc((lo|hi)&p).
    float part[2][NCLS];
#pragma unroll
    for (int bi = 0; bi < 2; bi++)
#pragma unroll
        for (int c = 0; c < NCLS; c++) part[bi][c] = 0.0f;

    if (tid < 250) {
#pragma unroll
        for (int i = 0; i < 4; i++) {
            int d = i * 250 + tid;                 // d < 1000
            uint32_t sig = g_sig[d];
            int siglo = sig & 31, sighi = (sig >> 5) & 31;
            uint4 pb4[6];
#pragma unroll
            for (int q = 0; q < 6; q++)
                pb4[q] = ((const uint4*)&g_posb[d * PWP])[q];   // words 0..23
            uint32_t pb24 = g_posb[d * PWP + 24];
            uint32_t pbw[PW];
#pragma unroll
            for (int q = 0; q < 6; q++) {
                pbw[q * 4 + 0] = pb4[q].x; pbw[q * 4 + 1] = pb4[q].y;
                pbw[q * 4 + 2] = pb4[q].z; pbw[q * 4 + 3] = pb4[q].w;
            }
            pbw[24] = pb24;
            int tpos = g_tpos[d];
            const float4* w4 = (const float4*)&g_wt[d * 12];
            float4 w0 = w4[0], w1 = w4[1], w2 = w4[2];
#pragma unroll
            for (int bi = 0; bi < 2; bi++) {
                int acc = 0;
#pragma unroll
                for (int q = 0; q < PW; q++) {
                    uint32_t a = MunT[bi][0][q][siglo];
                    uint32_t b = MunT[bi][1][q][sighi];
                    acc += __popc((a | b) & pbw[q]);
                }
                int csum = Cun[bi][0][siglo] + Cun[bi][1][sighi];
                int s = 4 * acc - 2 * csum - tpos;
                float enc = (s > 0) ? 1.0f : -1.0f;
                part[bi][0] += enc * w0.x; part[bi][1] += enc * w0.y;
                part[bi][2] += enc * w0.z; part[bi][3] += enc * w0.w;
                part[bi][4] += enc * w1.x; part[bi][5] += enc * w1.y;
                part[bi][6] += enc * w1.z; part[bi][7] += enc * w1.w;
                part[bi][8] += enc * w2.x; part[bi][9] += enc * w2.y;
            }
        }
    }

    // ---- deterministic reduction: warp shuffle + fixed-order smem sum ----
#pragma unroll
    for (int bi = 0; bi < 2; bi++) {
#pragma unroll
        for (int c = 0; c < NCLS; c++) {
            float v = part[bi][c];
            v += __shfl_down_sync(0xffffffffu, v, 16);
            v += __shfl_down_sync(0xffffffffu, v, 8);
            v += __shfl_down_sync(0xffffffffu, v, 4);
            v += __shfl_down_sync(0xffffffffu, v, 2);
            v += __shfl_down_sync(0xffffffffu, v, 1);
            if (lane == 0) wred[bi][warp][c] = v;
        }
    }
    __syncthreads();

    if (tid < 2 * NCLS) {
        int bi = tid / NCLS, c = tid % NCLS;
        float s = 0.0f;
#pragma unroll
        for (int w = 0; w < 8; w++) s += wred[bi][w][c];
        out[(blockIdx.x * 2 + bi) * NCLS + c] = s;
    }
}

// ---------------- launch ----------------
extern "C" void kernel_launch(void* const* d_in, const int* in_sizes, int n_in,
                              void* d_out, int out_size) {
    const float* x        = (const float*)d_in[0];   // [256, 28, 28]
    const float* position = (const float*)d_in[1];   // [784, 1000]
    const float* vt       = (const float*)d_in[2];   // [10, 1000]
    const float* W        = (const float*)d_in[3];   // [10, 1000]
    float* out = (float*)d_out;                      // [256, 10]

    pack_pos_kernel<<<25, 256>>>(position);
    prep_kernel<<<4, 256>>>(vt, W);
    hdc_kernel<<<128, 256>>>(x, out);
}

// round 7
// speedup vs baseline: 1.1544x; 1.0453x over previous
#include <cuda_runtime.h>
#include <cstdint>

#define DIMS   1000
#define NLEV   10
#define NPIX   784
#define NBATCH 256
#define NCLS   10
#define PW     25      // 784 pixels -> 25 x u32 words
#define PWP    28      // g_posb row stride in words (112B)

// ---------------- device scratch (no allocations allowed) ----------------
__device__ uint32_t g_posb[1024 * PWP];   // packed position sign bits, d-major rows

__device__ __forceinline__ uint32_t smem_u32(const void* p) {
    uint32_t a;
    asm("{ .reg .u64 t; cvta.to.shared.u64 t, %1; cvt.u32.u64 %0, t; }"
        : "=r"(a) : "l"(p));
    return a;
}

// ---------------- kernel A: pack position sign bits via cp.async.bulk ----
// CTA (w, qq): bulk-copies 8 rows (32KB) of position into smem, packs 8 bits
// per dim, stores them as byte qq of word w in g_posb. Byte-granular stores
// from different CTAs compose each u32 without RMW -> deterministic.
__global__ __launch_bounds__(256) void pack_kernel(const float* __restrict__ position) {
    __shared__ __align__(128) float buf[8 * DIMS];        // 32000 B
    __shared__ __align__(8) unsigned long long mbar;

    const int w   = blockIdx.x;            // 0..24
    const int qq  = blockIdx.y;            // 0..3
    const int tid = threadIdx.x;
    const int p0  = w * 32 + qq * 8;       // first pixel of this byte
    const bool active = (p0 < NPIX);       // 784 = 98*8: active => full 8 rows

    if (active) {
        uint32_t mb = smem_u32(&mbar);
        if (tid == 0) {
            asm volatile("mbarrier.init.shared.b64 [%0], %1;"
                         :: "r"(mb), "r"(1) : "memory");
        }
        __syncthreads();
        if (tid == 0) {
            const uint32_t bytes = 8 * DIMS * 4;   // 32000, 16B multiple
            asm volatile("mbarrier.arrive.expect_tx.shared.b64 _, [%0], %1;"
                         :: "r"(mb), "r"(bytes) : "memory");
            asm volatile(
                "cp.async.bulk.shared::cluster.global.mbarrier::complete_tx::bytes "
                "[%0], [%1], %2, [%3];"
                :: "r"(smem_u32(buf)),
                   "l"(position + (size_t)p0 * DIMS),
                   "r"(bytes), "r"(mb) : "memory");
        }
        // wait (parity 0)
        {
            uint32_t mb2 = smem_u32(&mbar);
            uint32_t done;
            asm volatile(
                "{\n\t.reg .pred p;\n\t"
                "mbarrier.try_wait.parity.acquire.cta.shared::cta.b64 p, [%1], 0;\n\t"
                "selp.b32 %0, 1, 0, p;\n\t}"
                : "=r"(done) : "r"(mb2) : "memory");
            while (!done) {
                asm volatile(
                    "{\n\t.reg .pred p;\n\t"
                    "mbarrier.try_wait.parity.acquire.cta.shared::cta.b64 p, [%1], 0, 0x989680;\n\t"
                    "selp.b32 %0, 1, 0, p;\n\t}"
                    : "=r"(done) : "r"(mb2) : "memory");
            }
        }
    }

    if (tid < 250) {
        const int d0 = tid * 4;
        uint32_t b0 = 0, b1 = 0, b2 = 0, b3 = 0;
        if (active) {
#pragma unroll
            for (int j = 0; j < 8; j++) {
                float4 v = ((const float4*)buf)[j * 250 + tid];
                b0 |= (v.x > 0.0f ? 1u : 0u) << j;
                b1 |= (v.y > 0.0f ? 1u : 0u) << j;
                b2 |= (v.z > 0.0f ? 1u : 0u) << j;
                b3 |= (v.w > 0.0f ? 1u : 0u) << j;
            }
        }
        unsigned char* gb = (unsigned char*)g_posb;
        const int off = w * 4 + qq;            // byte offset inside the row
        gb[(size_t)(d0 + 0) * (PWP * 4) + off] = (unsigned char)b0;
        gb[(size_t)(d0 + 1) * (PWP * 4) + off] = (unsigned char)b1;
        gb[(size_t)(d0 + 2) * (PWP * 4) + off] = (unsigned char)b2;
        gb[(size_t)(d0 + 3) * (PWP * 4) + off] = (unsigned char)b3;
    }
    // zero the 3 padding words of each row once (CTA (0,0) only)
    if (w == 0 && qq == 0 && tid < 250) {
        const int d0 = tid * 4;
#pragma unroll
        for (int k = 0; k < 4; k++) {
            g_posb[(d0 + k) * PWP + 25] = 0u;
            g_posb[(d0 + k) * PWP + 26] = 0u;
            g_posb[(d0 + k) * PWP + 27] = 0u;
        }
    }
}

// ---------------- kernel B: masks + transposed unions + popcount + head --
// prep folded in: tpos from pb popcount, sig from vt, classifier W read raw.
__global__ __launch_bounds__(256) void hdc_kernel(const float* __restrict__ x,
                                                  const float* __restrict__ vt,
                                                  const float* __restrict__ W,
                                                  float* __restrict__ out) {
    __shared__ uint32_t MunT[2][2][PW][32];   // [bi][half][word][sg] 12.5KB
    __shared__ int      Cun[2][2][32];
    __shared__ __align__(16) uint32_t mask[2][NLEV][PWP];
    __shared__ int      cnt[2][NLEV];
    __shared__ float    wred[2][8][NCLS];

    const int tid  = threadIdx.x;
    const int lane = tid & 31;
    const int warp = tid >> 5;

    for (int i = tid; i < 2 * NLEV * PWP; i += 256)
        ((uint32_t*)mask)[i] = 0u;
    __syncthreads();

    // ---- phase 1: per-batch level masks via ballot ----
#pragma unroll
    for (int bi = 0; bi < 2; bi++) {
        const float* xb = x + (blockIdx.x * 2 + bi) * NPIX;
        for (int base = 0; base < 1024; base += 256) {
            int p = base + tid;
            int lvl = -1;
            if (p < NPIX) {
                float xv = xb[p];
                int q = (int)rintf(xv * 9.0f);   // round-half-even == jnp.round
                q = q < 0 ? 0 : (q > 9 ? 9 : q);
                lvl = q;
            }
            int word = (base >> 5) + warp;
#pragma unroll
            for (int l = 0; l < NLEV; l++) {
                unsigned bm = __ballot_sync(0xffffffffu, lvl == l);
                if (lane == 0 && word < PW) mask[bi][l][word] = bm;
            }
        }
    }
    __syncthreads();

    if (tid < 2 * NLEV) {
        int bi = tid / NLEV, l = tid % NLEV;
        int c = 0;
#pragma unroll
        for (int w = 0; w < PW; w++) c += __popc(mask[bi][l][w]);
        cnt[bi][l] = c;
    }
    __syncthreads();

    // ---- phase 2: unions per 5-bit half signature (sg = bank axis) ----
    if (tid < 128) {
        int bi   = tid >> 6;
        int half = (tid >> 5) & 1;
        int sg   = tid & 31;
        int lbase = half * 5;
        int c = 0;
#pragma unroll
        for (int l = 0; l < 5; l++)
            if (sg & (1 << l)) c += cnt[bi][lbase + l];
        Cun[bi][half][sg] = c;
#pragma unroll
        for (int q = 0; q < PW; q++) {
            uint32_t r = 0u;
#pragma unroll
            for (int l = 0; l < 5; l++)
                if (sg & (1 << l)) r |= mask[bi][lbase + l][q];
            MunT[bi][half][q][sg] = r;
        }
    }
    __syncthreads();

    // ---- phase 3: popcount core + inline prep + classifier partials ----
    float part[2][NCLS];
#pragma unroll
    for (int bi = 0; bi < 2; bi++)
#pragma unroll
        for (int c = 0; c < NCLS; c++) part[bi][c] = 0.0f;

    if (tid < 250) {
#pragma unroll
        for (int i = 0; i < 4; i++) {
            int d = i * 250 + tid;                 // d < 1000
            // position bit-rows (25 words)
            uint32_t pbw[PW];
#pragma unroll
            for (int q = 0; q < 6; q++) {
                uint4 v = ((const uint4*)&g_posb[d * PWP])[q];
                pbw[q * 4 + 0] = v.x; pbw[q * 4 + 1] = v.y;
                pbw[q * 4 + 2] = v.z; pbw[q * 4 + 3] = v.w;
            }
            pbw[24] = g_posb[d * PWP + 24];
            // tpos (inline prep)
            int totp = 0;
#pragma unroll
            for (int q = 0; q < PW; q++) totp += __popc(pbw[q]);
            int tpos = 2 * totp - NPIX;
            // value-table signature (inline prep; vt is L2-resident)
            uint32_t sig = 0;
#pragma unroll
            for (int l = 0; l < NLEV; l++)
                sig |= (vt[l * DIMS + d] > 0.0f ? 1u : 0u) << l;
            int siglo = sig & 31, sighi = (sig >> 5) & 31;
            // classifier column (coalesced, L2-resident)
            float wv[NCLS];
#pragma unroll
            for (int c = 0; c < NCLS; c++) wv[c] = W[c * DIMS + d];

#pragma unroll
            for (int bi = 0; bi < 2; bi++) {
                int acc = 0;
#pragma unroll
                for (int q = 0; q < PW; q++) {
                    uint32_t a = MunT[bi][0][q][siglo];
                    uint32_t b = MunT[bi][1][q][sighi];
                    acc += __popc((a | b) & pbw[q]);
                }
                int csum = Cun[bi][0][siglo] + Cun[bi][1][sighi];
                int s = 4 * acc - 2 * csum - tpos;
                float enc = (s > 0) ? 1.0f : -1.0f;
#pragma unroll
                for (int c = 0; c < NCLS; c++) part[bi][c] += enc * wv[c];
            }
        }
    }

    // ---- deterministic reduction ----
#pragma unroll
    for (int bi = 0; bi < 2; bi++) {
#pragma unroll
        for (int c = 0; c < NCLS; c++) {
            float v = part[bi][c];
            v += __shfl_down_sync(0xffffffffu, v, 16);
            v += __shfl_down_sync(0xffffffffu, v, 8);
            v += __shfl_down_sync(0xffffffffu, v, 4);
            v += __shfl_down_sync(0xffffffffu, v, 2);
            v += __shfl_down_sync(0xffffffffu, v, 1);
            if (lane == 0) wred[bi][warp][c] = v;
        }
    }
    __syncthreads();

    if (tid < 2 * NCLS) {
        int bi = tid / NCLS, c = tid % NCLS;
        float s = 0.0f;
#pragma unroll
        for (int w = 0; w < 8; w++) s += wred[bi][w][c];
        out[(blockIdx.x * 2 + bi) * NCLS + c] = s;
    }
}

// ---------------- launch ----------------
extern "C" void kernel_launch(void* const* d_in, const int* in_sizes, int n_in,
                              void* d_out, int out_size) {
    const float* x        = (const float*)d_in[0];   // [256, 28, 28]
    const float* position = (const float*)d_in[1];   // [784, 1000]
    const float* vt       = (const float*)d_in[2];   // [10, 1000]
    const float* W        = (const float*)d_in[3];   // [10, 1000]
    float* out = (float*)d_out;                      // [256, 10]

    pack_kernel<<<dim3(25, 4), 256>>>(position);
    hdc_kernel<<<128, 256>>>(x, vt, W, out);
}

// round 9
// speedup vs baseline: 1.3055x; 1.1309x over previous
#include <cuda_runtime.h>
#include <cstdint>

#define DIMS   1000
#define NLEV   10
#define NPIX   784
#define NBATCH 256
#define NCLS   10
#define PW     25      // 784 pixels -> 25 x u32 words
#define PWP    28      // g_posb row stride in words (112B)

// ---------------- device scratch (no allocations allowed) ----------------
__device__ uint32_t g_posb[1024 * PWP];   // packed position sign bits, d-major rows

__device__ __forceinline__ uint32_t smem_u32(const void* p) {
    uint32_t a;
    asm("{ .reg .u64 t; cvta.to.shared.u64 t, %1; cvt.u32.u64 %0, t; }"
        : "=r"(a) : "l"(p));
    return a;
}

// ---------------- kernel A: pack position sign bits via cp.async.bulk ----
// CTA (w, qq): bulk-copies 8 rows (32KB) of position into smem, packs 8 bits
// per dim, stores them as byte qq of word w in g_posb (byte stores compose
// words across CTAs without RMW -> deterministic).
__global__ __launch_bounds__(256) void pack_kernel(const float* __restrict__ position) {
    __shared__ __align__(128) float buf[8 * DIMS];        // 32000 B
    __shared__ __align__(8) unsigned long long mbar;

    const int w   = blockIdx.x;            // 0..24
    const int qq  = blockIdx.y;            // 0..3
    const int tid = threadIdx.x;
    const int p0  = w * 32 + qq * 8;       // first pixel of this byte
    const bool active = (p0 < NPIX);       // 784 = 98*8: active => full 8 rows

    if (active) {
        uint32_t mb = smem_u32(&mbar);
        if (tid == 0) {
            asm volatile("mbarrier.init.shared.b64 [%0], %1;"
                         :: "r"(mb), "r"(1) : "memory");
        }
        __syncthreads();
        if (tid == 0) {
            const uint32_t bytes = 8 * DIMS * 4;   // 32000, 16B multiple
            asm volatile("mbarrier.arrive.expect_tx.shared.b64 _, [%0], %1;"
                         :: "r"(mb), "r"(bytes) : "memory");
            asm volatile(
                "cp.async.bulk.shared::cluster.global.mbarrier::complete_tx::bytes "
                "[%0], [%1], %2, [%3];"
                :: "r"(smem_u32(buf)),
                   "l"(position + (size_t)p0 * DIMS),
                   "r"(bytes), "r"(mb) : "memory");
        }
        uint32_t mb2 = smem_u32(&mbar);
        uint32_t done;
        asm volatile(
            "{\n\t.reg .pred p;\n\t"
            "mbarrier.try_wait.parity.acquire.cta.shared::cta.b64 p, [%1], 0;\n\t"
            "selp.b32 %0, 1, 0, p;\n\t}"
            : "=r"(done) : "r"(mb2) : "memory");
        while (!done) {
            asm volatile(
                "{\n\t.reg .pred p;\n\t"
                "mbarrier.try_wait.parity.acquire.cta.shared::cta.b64 p, [%1], 0, 0x989680;\n\t"
                "selp.b32 %0, 1, 0, p;\n\t}"
                : "=r"(done) : "r"(mb2) : "memory");
        }
    }

    if (tid < 250) {
        const int d0 = tid * 4;
        uint32_t b0 = 0, b1 = 0, b2 = 0, b3 = 0;
        if (active) {
#pragma unroll
            for (int j = 0; j < 8; j++) {
                float4 v = ((const float4*)buf)[j * 250 + tid];
                b0 |= (v.x > 0.0f ? 1u : 0u) << j;
                b1 |= (v.y > 0.0f ? 1u : 0u) << j;
                b2 |= (v.z > 0.0f ? 1u : 0u) << j;
                b3 |= (v.w > 0.0f ? 1u : 0u) << j;
            }
        }
        unsigned char* gb = (unsigned char*)g_posb;
        const int off = w * 4 + qq;            // byte offset inside the row
        gb[(size_t)(d0 + 0) * (PWP * 4) + off] = (unsigned char)b0;
        gb[(size_t)(d0 + 1) * (PWP * 4) + off] = (unsigned char)b1;
        gb[(size_t)(d0 + 2) * (PWP * 4) + off] = (unsigned char)b2;
        gb[(size_t)(d0 + 3) * (PWP * 4) + off] = (unsigned char)b3;
    }
    if (w == 0 && qq == 0 && tid < 250) {
        const int d0 = tid * 4;
#pragma unroll
        for (int k = 0; k < 4; k++) {
            g_posb[(d0 + k) * PWP + 25] = 0u;
            g_posb[(d0 + k) * PWP + 26] = 0u;
            g_posb[(d0 + k) * PWP + 27] = 0u;
        }
    }
}

// ---------------- kernel B: 256 CTAs = one batch each --------------------
// Each CTA: ballots + union tables for its batch, then 4 dim-blocks of
// popcount + classifier per thread; writes its own out row (no atomics).
__global__ __launch_bounds__(256) void hdc_kernel(const float* __restrict__ x,
                                                  const float* __restrict__ vt,
                                                  const float* __restrict__ W,
                                                  float* __restrict__ out) {
    __shared__ uint32_t MunT[2][PW][32];      // [half][word][sg]  6.4KB
    __shared__ int      Cun[2][32];
    __shared__ __align__(16) uint32_t mask[NLEV][PWP];
    __shared__ int      cnt[NLEV];
    __shared__ float    wred[8][NCLS];

    const int b    = blockIdx.x;              // batch
    const int tid  = threadIdx.x;
    const int lane = tid & 31;
    const int warp = tid >> 5;

    // hoisted pixel loads (4 independent rounds)
    const float* xb = x + b * NPIX;
    float xv[4];
#pragma unroll
    for (int r = 0; r < 4; r++) {
        int p = r * 256 + tid;
        xv[r] = (p < NPIX) ? xb[p] : -1.0f;
    }

    for (int i = tid; i < NLEV * PWP; i += 256)
        ((uint32_t*)mask)[i] = 0u;
    __syncthreads();

    // ---- phase 1: level masks via ballot ----
#pragma unroll
    for (int r = 0; r < 4; r++) {
        int p = r * 256 + tid;
        int lvl = -1;
        if (p < NPIX) {
            int q = (int)rintf(xv[r] * 9.0f);     // round-half-even == jnp.round
            q = q < 0 ? 0 : (q > 9 ? 9 : q);
            lvl = q;
        }
        int word = r * 8 + warp;
#pragma unroll
        for (int l = 0; l < NLEV; l++) {
            unsigned bm = __ballot_sync(0xffffffffu, lvl == l);
            if (lane == 0 && word < PW) mask[l][word] = bm;
        }
    }
    __syncthreads();

    if (tid < NLEV) {
        int c = 0;
#pragma unroll
        for (int w = 0; w < PW; w++) c += __popc(mask[tid][w]);
        cnt[tid] = c;
    }
    __syncthreads();

    // ---- phase 2: unions per 5-bit half signature (sg = bank axis) ----
    if (tid < 64) {
        int half = tid >> 5;
        int sg   = tid & 31;
        int lbase = half * 5;
        int c = 0;
#pragma unroll
        for (int l = 0; l < 5; l++)
            if (sg & (1 << l)) c += cnt[lbase + l];
        Cun[half][sg] = c;
#pragma unroll
        for (int q = 0; q < PW; q++) {
            uint32_t r = 0u;
#pragma unroll
            for (int l = 0; l < 5; l++)
                if (sg & (1 << l)) r |= mask[lbase + l][q];
            MunT[half][q][sg] = r;
        }
    }
    __syncthreads();

    // ---- phase 3: popcount core + inline prep + classifier partials ----
    float part[NCLS];
#pragma unroll
    for (int c = 0; c < NCLS; c++) part[c] = 0.0f;

    if (tid < 250) {
#pragma unroll
        for (int i = 0; i < 4; i++) {
            int d = i * 250 + tid;                 // d < 1000
            uint32_t pbw[PW];
#pragma unroll
            for (int q = 0; q < 6; q++) {
                uint4 v = ((const uint4*)&g_posb[d * PWP])[q];
                pbw[q * 4 + 0] = v.x; pbw[q * 4 + 1] = v.y;
                pbw[q * 4 + 2] = v.z; pbw[q * 4 + 3] = v.w;
            }
            pbw[24] = g_posb[d * PWP + 24];
            uint32_t sig = 0;
#pragma unroll
            for (int l = 0; l < NLEV; l++)
                sig |= (vt[l * DIMS + d] > 0.0f ? 1u : 0u) << l;
            int siglo = sig & 31, sighi = (sig >> 5) & 31;
            float wv[NCLS];
#pragma unroll
            for (int c = 0; c < NCLS; c++) wv[c] = W[c * DIMS + d];

            int tot = 0, acc = 0;
#pragma unroll
            for (int q = 0; q < PW; q++) {
                tot += __popc(pbw[q]);
                uint32_t u = MunT[0][q][siglo] | MunT[1][q][sighi];
                acc += __popc(u & pbw[q]);
            }
            int csum = Cun[0][siglo] + Cun[1][sighi];
            int s = 4 * acc - 2 * csum - (2 * tot - NPIX);
            float enc = (s > 0) ? 1.0f : -1.0f;
#pragma unroll
            for (int c = 0; c < NCLS; c++) part[c] += enc * wv[c];
        }
    }

    // ---- deterministic reduction ----
#pragma unroll
    for (int c = 0; c < NCLS; c++) {
        float v = part[c];
        v += __shfl_down_sync(0xffffffffu, v, 16);
        v += __shfl_down_sync(0xffffffffu, v, 8);
        v += __shfl_down_sync(0xffffffffu, v, 4);
        v += __shfl_down_sync(0xffffffffu, v, 2);
        v += __shfl_down_sync(0xffffffffu, v, 1);
        if (lane == 0) wred[warp][c] = v;
    }
    __syncthreads();

    if (tid < NCLS) {
        float s = 0.0f;
#pragma unroll
        for (int w = 0; w < 8; w++) s += wred[w][tid];
        out[b * NCLS + tid] = s;
    }
}

// ---------------- launch ----------------
extern "C" void kernel_launch(void* const* d_in, const int* in_sizes, int n_in,
                              void* d_out, int out_size) {
    const float* x        = (const float*)d_in[0];   // [256, 28, 28]
    const float* position = (const float*)d_in[1];   // [784, 1000]
    const float* vt       = (const float*)d_in[2];   // [10, 1000]
    const float* W        = (const float*)d_in[3];   // [10, 1000]
    float* out = (float*)d_out;                      // [256, 10]

    pack_kernel<<<dim3(25, 4), 256>>>(position);
    hdc_kernel<<<256, 256>>>(x, vt, W, out);
}